// round 2
// baseline (speedup 1.0000x reference)
#include <cuda_runtime.h>
#include <math.h>

// StructureGraphMessagePassing — edge-sparse reformulation, FP32 SIMT GEMMs.
// N=64 nodes, D=1024, E=1024 edges, T=2 iterations.
// Off-edge relation state is provably dead (masked softmax + edge-only readers),
// so the whole recursion runs on the E=1024 edge rows.

namespace {
constexpr int D  = 1024;
constexpr int NV = 64;
constexpr int NE = 1024;

constexpr size_t M1 = 1048576;       // 1024*1024 floats
constexpr size_t O_W14   = 0;        // W1+W4 of W_rel_joint
constexpr size_t O_W24   = 1 * M1;   // W2-W4 of W_rel_joint
constexpr size_t O_WR2ST = 2 * M1;   // W_r2s transposed
constexpr size_t O_WR2OT = 3 * M1;   // W_r2o transposed
constexpr size_t O_RCA   = 4 * M1;   // rel_ctx edges (ping)
constexpr size_t O_RCB   = 5 * M1;   // rel_ctx edges (pong)
constexpr size_t O_RJ    = 6 * M1;   // rj at edges
constexpr size_t O_CC    = 7 * M1;   // rj @ Wr^T at edges
constexpr size_t O_RELJ  = 8 * M1;   // rel_j at edges
constexpr size_t O_RTRC  = 9 * M1;   // rvf * rc elementwise
constexpr size_t O_VJCAT = 10 * M1;              // 64 x 4096
constexpr size_t SZ      = 65536;                // 64 x 1024
constexpr size_t O_VJ    = O_VJCAT + 262144;
constexpr size_t O_A0    = O_VJ   + SZ;          // vj @ Ws^T
constexpr size_t O_B0    = O_A0   + SZ;          // vj @ Wo^T
constexpr size_t O_QS    = O_B0   + SZ;
constexpr size_t O_QO    = O_QS   + SZ;
constexpr size_t O_QS2   = O_QO   + SZ;
constexpr size_t O_QO2   = O_QS2  + SZ;
constexpr size_t O_CTXS  = O_QO2  + SZ;
constexpr size_t O_CTXO  = O_CTXS + SZ;
constexpr size_t O_VCX_A = O_CTXO + SZ;          // vctx ping
constexpr size_t O_VCX_B = O_VCX_A + SZ;         // vctx pong
constexpr size_t O_SS    = O_VCX_B + SZ;
constexpr size_t O_SO    = O_SS + 1024;
constexpr size_t O_WS    = O_SS + 2048;
constexpr size_t O_WO    = O_SS + 3072;
constexpr size_t TOTAL   = O_SS + 4096;
}  // namespace

__device__ float g_buf[TOTAL];

// ---------------------------------------------------------------------------
// Multi-segment multi-job NT GEMM:  C = sum_s A_s @ B_s^T   (fp32)
// A_s: (M,K_s) lda ; B_s: (N,K_s) ldb ; C: (M,N) ldc. M,N mult of 64, K mult 16.
// grid = (N/64, M/64, njobs), 256 threads, 4x4 microtile, double-buffered smem.
// ---------------------------------------------------------------------------
struct Seg { const float* A; const float* B; int lda, ldb, K; };
struct Job { Seg sg[3]; float* C; int ldc; int nseg; };
struct Batch { Job j[4]; };

__global__ __launch_bounds__(256, 2) void gemm_nt(Batch batch) {
    const Job job = batch.j[blockIdx.z];
    __shared__ float As[2][16][64];
    __shared__ float Bs[2][16][64];
    const int tid = threadIdx.x;
    const int tx = tid & 15, ty = tid >> 4;
    const int m0 = blockIdx.y << 6;
    const int n0 = blockIdx.x << 6;
    const int lr = tid >> 2;
    const int lk = (tid & 3) << 2;

    float acc[16];
#pragma unroll
    for (int i = 0; i < 16; ++i) acc[i] = 0.f;

    for (int s = 0; s < job.nseg; ++s) {
        const Seg sg = job.sg[s];
        const float* Ap = sg.A + (size_t)(m0 + lr) * sg.lda + lk;
        const float* Bp = sg.B + (size_t)(n0 + lr) * sg.ldb + lk;
        const int T = sg.K >> 4;

        float4 a = *(const float4*)Ap;
        float4 b = *(const float4*)Bp;
        As[0][lk + 0][lr] = a.x; As[0][lk + 1][lr] = a.y;
        As[0][lk + 2][lr] = a.z; As[0][lk + 3][lr] = a.w;
        Bs[0][lk + 0][lr] = b.x; Bs[0][lk + 1][lr] = b.y;
        Bs[0][lk + 2][lr] = b.z; Bs[0][lk + 3][lr] = b.w;
        __syncthreads();

        int buf = 0;
        for (int t = 0; t < T; ++t) {
            float4 na, nb;
            if (t + 1 < T) {
                na = *(const float4*)(Ap + (size_t)(t + 1) * 16);
                nb = *(const float4*)(Bp + (size_t)(t + 1) * 16);
            }
#pragma unroll
            for (int kk = 0; kk < 16; ++kk) {
                float4 av = *(const float4*)&As[buf][kk][ty << 2];
                float4 bv = *(const float4*)&Bs[buf][kk][tx << 2];
                acc[0]  += av.x * bv.x; acc[1]  += av.x * bv.y;
                acc[2]  += av.x * bv.z; acc[3]  += av.x * bv.w;
                acc[4]  += av.y * bv.x; acc[5]  += av.y * bv.y;
                acc[6]  += av.y * bv.z; acc[7]  += av.y * bv.w;
                acc[8]  += av.z * bv.x; acc[9]  += av.z * bv.y;
                acc[10] += av.z * bv.z; acc[11] += av.z * bv.w;
                acc[12] += av.w * bv.x; acc[13] += av.w * bv.y;
                acc[14] += av.w * bv.z; acc[15] += av.w * bv.w;
            }
            if (t + 1 < T) {
                buf ^= 1;
                As[buf][lk + 0][lr] = na.x; As[buf][lk + 1][lr] = na.y;
                As[buf][lk + 2][lr] = na.z; As[buf][lk + 3][lr] = na.w;
                Bs[buf][lk + 0][lr] = nb.x; Bs[buf][lk + 1][lr] = nb.y;
                Bs[buf][lk + 2][lr] = nb.z; Bs[buf][lk + 3][lr] = nb.w;
                __syncthreads();
            }
        }
        __syncthreads();
    }

    float* C = job.C + (size_t)(m0 + (ty << 2)) * job.ldc + n0 + (tx << 2);
#pragma unroll
    for (int i = 0; i < 4; ++i) {
        float4 v = make_float4(acc[i * 4 + 0], acc[i * 4 + 1],
                               acc[i * 4 + 2], acc[i * 4 + 3]);
        *(float4*)(C + (size_t)i * job.ldc) = v;
    }
}

// ---------------------------------------------------------------------------
// Glue kernels
// ---------------------------------------------------------------------------
__global__ void k_prep(const float* __restrict__ Wrj,
                       const float* __restrict__ Wr2s,
                       const float* __restrict__ Wr2o,
                       const float* __restrict__ rvf,
                       const float* __restrict__ vf) {
    int idx = blockIdx.x * blockDim.x + threadIdx.x;
    if (idx >= D * D) return;
    int n = idx >> 10, k = idx & 1023;
    const float* row = Wrj + (size_t)n * 4096;
    g_buf[O_W14 + idx] = row[k] + row[3072 + k];
    g_buf[O_W24 + idx] = row[1024 + k] - row[3072 + k];
    g_buf[O_WR2ST + idx] = Wr2s[(size_t)k * 1024 + n];
    g_buf[O_WR2OT + idx] = Wr2o[(size_t)k * 1024 + n];
    g_buf[O_RCA + idx] = rvf[idx];                 // E*D == D*D here
    if (idx < NV * D) g_buf[O_VCX_A + idx] = vf[idx];
}

// vjcat = [vf, vctx, vf*vctx, vctx-vf]  (64 x 4096)
__global__ void k_vjcat(const float* __restrict__ vf, const float* __restrict__ vcx) {
    int idx = blockIdx.x * blockDim.x + threadIdx.x;  // 65536
    int m = idx >> 10, d = idx & 1023;
    float a = vf[idx];
    float c = vcx[idx];
    size_t o = O_VJCAT + (size_t)m * 4096 + d;
    g_buf[o]        = a;
    g_buf[o + 1024] = c;
    g_buf[o + 2048] = a * c;
    g_buf[o + 3072] = c - a;
}

__global__ void k_rtrc(const float* __restrict__ rvf, const float* __restrict__ rc) {
    int idx = blockIdx.x * blockDim.x + threadIdx.x;  // 1M
    g_buf[O_RTRC + idx] = rvf[idx] * rc[idx];
}

// rel_j at edges = A0[i] + B0[j] + cc[e]
__global__ void k_relj(const int* __restrict__ eidx) {
    int idx = blockIdx.x * blockDim.x + threadIdx.x;  // 1M
    int e = idx >> 10, d = idx & 1023;
    int ei = eidx[e];
    int i = ei >> 6, j = ei & 63;
    g_buf[O_RELJ + idx] = g_buf[O_A0 + ((size_t)i << 10) + d] +
                          g_buf[O_B0 + ((size_t)j << 10) + d] +
                          g_buf[O_CC + idx];
}

// per-edge scores: ss[e]=<qs2[i],relj[e]>/32 ; so[e]=<qo2[j],relj[e]>/32
__global__ void k_scores(const int* __restrict__ eidx) {
    int e = blockIdx.x, tid = threadIdx.x;
    int ei = eidx[e];
    int i = ei >> 6, j = ei & 63;
    const float* r = g_buf + O_RELJ + ((size_t)e << 10);
    const float* a = g_buf + O_QS2 + ((size_t)i << 10);
    const float* b = g_buf + O_QO2 + ((size_t)j << 10);
    float s1 = 0.f, s2 = 0.f;
    for (int d = tid; d < 1024; d += 256) {
        float rv = r[d];
        s1 += a[d] * rv;
        s2 += b[d] * rv;
    }
    __shared__ float sh[2][256];
    sh[0][tid] = s1; sh[1][tid] = s2;
    __syncthreads();
    for (int st = 128; st > 0; st >>= 1) {
        if (tid < st) { sh[0][tid] += sh[0][tid + st]; sh[1][tid] += sh[1][tid + st]; }
        __syncthreads();
    }
    if (tid == 0) {
        g_buf[O_SS + e] = sh[0][0] * 0.03125f;
        g_buf[O_SO + e] = sh[1][0] * 0.03125f;
    }
}

// blocks 0..63: row softmax of ss; blocks 64..127: col softmax of so
__global__ void k_softmax(const int* __restrict__ conn) {
    int b = blockIdx.x, lane = threadIdx.x;
    bool isRow = b < 64;
    int idx = isRow ? b : b - 64;
    int e0 = isRow ? conn[idx * 64 + lane]        : conn[lane * 64 + idx];
    int e1 = isRow ? conn[idx * 64 + lane + 32]   : conn[(lane + 32) * 64 + idx];
    size_t so = isRow ? O_SS : O_SO;
    float v0 = (e0 >= 0) ? g_buf[so + e0] : -1e30f;
    float v1 = (e1 >= 0) ? g_buf[so + e1] : -1e30f;
    float m = fmaxf(v0, v1);
    for (int o = 16; o > 0; o >>= 1) m = fmaxf(m, __shfl_xor_sync(0xffffffffu, m, o));
    float x0 = (e0 >= 0) ? expf(v0 - m) : 0.f;
    float x1 = (e1 >= 0) ? expf(v1 - m) : 0.f;
    float s = x0 + x1;
    for (int o = 16; o > 0; o >>= 1) s += __shfl_xor_sync(0xffffffffu, s, o);
    float inv = 1.f / s;
    size_t wo = isRow ? O_WS : O_WO;
    if (e0 >= 0) g_buf[wo + e0] = x0 * inv;
    if (e1 >= 0) g_buf[wo + e1] = x1 * inv;
}

// ctx gathers: ctxs[n] = sum_j ws[e]*relj[e], ctxo[n] = sum_i wo[e]*relj[e]
__global__ void k_ctx(const int* __restrict__ conn) {
    int n = blockIdx.x, tid = threadIdx.x;
    float accS[4] = {0.f, 0.f, 0.f, 0.f};
    float accO[4] = {0.f, 0.f, 0.f, 0.f};
    for (int p = 0; p < 64; ++p) {
        int eS = conn[n * 64 + p];
        if (eS >= 0) {
            float w = g_buf[O_WS + eS];
            const float* r = g_buf + O_RELJ + ((size_t)eS << 10);
#pragma unroll
            for (int c = 0; c < 4; ++c) accS[c] += w * r[tid + 256 * c];
        }
        int eO = conn[p * 64 + n];
        if (eO >= 0) {
            float w = g_buf[O_WO + eO];
            const float* r = g_buf + O_RELJ + ((size_t)eO << 10);
#pragma unroll
            for (int c = 0; c < 4; ++c) accO[c] += w * r[tid + 256 * c];
        }
    }
#pragma unroll
    for (int c = 0; c < 4; ++c) {
        int d = tid + 256 * c;
        g_buf[O_CTXS + ((size_t)n << 10) + d] = accS[c];
        g_buf[O_CTXO + ((size_t)n << 10) + d] = accO[c];
    }
}

// v_out epilogue: bias + deg==0 passthrough
__global__ void k_voutepi(const int* __restrict__ conn,
                          const float* __restrict__ bnode,
                          const float* __restrict__ vf,
                          float* __restrict__ vout) {
    int i = blockIdx.x, tid = threadIdx.x;
    __shared__ int s_deg;
    if (tid == 0) {
        int dc = 0;
        for (int p = 0; p < 64; ++p)
            dc += (conn[i * 64 + p] >= 0) + (conn[p * 64 + i] >= 0);
        s_deg = dc;
    }
    __syncthreads();
    for (int d = tid; d < 1024; d += 256) {
        float v = vout[((size_t)i << 10) + d] + bnode[d];
        if (s_deg == 0) v = vf[((size_t)i << 10) + d];
        vout[((size_t)i << 10) + d] = v;
    }
}

// ---------------------------------------------------------------------------
static inline Job mkjob1(const float* A, const float* Bm, int lda, int ldb, int K,
                         float* C, int ldc) {
    Job j{};
    j.sg[0] = Seg{A, Bm, lda, ldb, K};
    j.nseg = 1; j.C = C; j.ldc = ldc;
    return j;
}

extern "C" void kernel_launch(void* const* d_in, const int* in_sizes, int n_in,
                              void* d_out, int out_size) {
    (void)in_sizes; (void)n_in; (void)out_size;
    const float* vf     = (const float*)d_in[0];
    const float* rvf    = (const float*)d_in[1];
    const int*   conn   = (const int*)d_in[2];
    const int*   eidx   = (const int*)d_in[4];
    const float* W_sub  = (const float*)d_in[5];
    const float* W_obj  = (const float*)d_in[6];
    const float* W_joint= (const float*)d_in[9];
    const float* W_ctx  = (const float*)d_in[10];
    const float* W_ru   = (const float*)d_in[11];  // (1024 x 3072)
    const float* W_rj   = (const float*)d_in[12];  // (1024 x 4096)
    const float* W_rc   = (const float*)d_in[13];  // (1024 x 2048)
    const float* W_node = (const float*)d_in[14];  // (1024 x 2048)
    const float* b_node = (const float*)d_in[15];
    const float* W_fac  = (const float*)d_in[16];  // (1024 x 2048)
    float* out = (float*)d_out;                    // rel_out (1024x1024) then v_out (64x1024)

    float* B = nullptr;
    cudaGetSymbolAddress((void**)&B, g_buf);

    k_prep<<<4096, 256>>>(W_rj, (const float*)d_in[7], (const float*)d_in[8], rvf, vf);

    for (int t = 0; t < 2; ++t) {
        float* rcIn   = B + (t == 0 ? O_RCA : O_RCB);
        float* rcOut  = B + (t == 0 ? O_RCB : O_RCA);
        float* vcxIn  = B + (t == 0 ? O_VCX_A : O_VCX_B);
        float* vcxOut = B + (t == 0 ? O_VCX_B : O_VCX_A);

        // vj = [vf,vctx,vf*vctx,vctx-vf] @ W_joint^T
        k_vjcat<<<256, 256>>>(vf, vcxIn);
        {
            Batch bt{};
            bt.j[0] = mkjob1(B + O_VJCAT, W_joint, 4096, 4096, 4096, B + O_VJ, 1024);
            gemm_nt<<<dim3(16, 1, 1), 256>>>(bt);
        }

        // rj(edges) = rvf@(W1+W4)^T + rc@(W2-W4)^T + (rvf*rc)@W3^T
        k_rtrc<<<4096, 256>>>(rvf, rcIn);
        {
            Batch bt{};
            Job j{};
            j.sg[0] = Seg{rvf,        B + O_W14,   1024, 1024, 1024};
            j.sg[1] = Seg{rcIn,       B + O_W24,   1024, 1024, 1024};
            j.sg[2] = Seg{B + O_RTRC, W_rj + 2048, 1024, 4096, 1024};
            j.nseg = 3; j.C = B + O_RJ; j.ldc = 1024;
            bt.j[0] = j;
            gemm_nt<<<dim3(16, 16, 1), 256>>>(bt);
        }

        // cc = rj @ Wr^T
        {
            Batch bt{};
            bt.j[0] = mkjob1(B + O_RJ, W_ru + 2048, 1024, 3072, 1024, B + O_CC, 1024);
            gemm_nt<<<dim3(16, 16, 1), 256>>>(bt);
        }

        // 64-row projections, stage 1
        {
            Batch bt{};
            bt.j[0] = mkjob1(B + O_VJ, W_ru,        1024, 3072, 1024, B + O_A0, 1024);
            bt.j[1] = mkjob1(B + O_VJ, W_ru + 1024, 1024, 3072, 1024, B + O_B0, 1024);
            bt.j[2] = mkjob1(B + O_VJ, W_sub,       1024, 1024, 1024, B + O_QS, 1024);
            bt.j[3] = mkjob1(B + O_VJ, W_obj,       1024, 1024, 1024, B + O_QO, 1024);
            gemm_nt<<<dim3(16, 1, 4), 256>>>(bt);
        }
        // stage 2: qs2 = qs @ W_r2s, qo2 = qo @ W_r2o
        {
            Batch bt{};
            bt.j[0] = mkjob1(B + O_QS, B + O_WR2ST, 1024, 1024, 1024, B + O_QS2, 1024);
            bt.j[1] = mkjob1(B + O_QO, B + O_WR2OT, 1024, 1024, 1024, B + O_QO2, 1024);
            gemm_nt<<<dim3(16, 1, 2), 256>>>(bt);
        }

        k_relj<<<4096, 256>>>(eidx);
        k_scores<<<1024, 256>>>(eidx);
        k_softmax<<<128, 32>>>(conn);
        k_ctx<<<64, 256>>>(conn);

        // vctx' = vctx@Wc_a^T + ctxs@Wc_b^T + ctxo@Wc_c^T
        {
            Batch bt{};
            Job j{};
            j.sg[0] = Seg{vcxIn,      W_ctx,        1024, 3072, 1024};
            j.sg[1] = Seg{B + O_CTXS, W_ctx + 1024, 1024, 3072, 1024};
            j.sg[2] = Seg{B + O_CTXO, W_ctx + 2048, 1024, 3072, 1024};
            j.nseg = 3; j.C = vcxOut; j.ldc = 1024;
            bt.j[0] = j;
            gemm_nt<<<dim3(16, 1, 1), 256>>>(bt);
        }

        // rc' = rc@Wc1^T + rel_j@Wc2^T
        {
            Batch bt{};
            Job j{};
            j.sg[0] = Seg{rcIn,       W_rc,        1024, 2048, 1024};
            j.sg[1] = Seg{B + O_RELJ, W_rc + 1024, 1024, 2048, 1024};
            j.nseg = 2; j.C = rcOut; j.ldc = 1024;
            bt.j[0] = j;
            gemm_nt<<<dim3(16, 16, 1), 256>>>(bt);
        }
    }

    // rel_out = [rvf, rc_final] @ W_factor^T   (rc_final is in RCA after t=1)
    {
        Batch bt{};
        Job j{};
        j.sg[0] = Seg{rvf,        W_fac,        1024, 2048, 1024};
        j.sg[1] = Seg{B + O_RCA,  W_fac + 1024, 1024, 2048, 1024};
        j.nseg = 2; j.C = out; j.ldc = 1024;
        bt.j[0] = j;
        gemm_nt<<<dim3(16, 16, 1), 256>>>(bt);
    }
    // v_out = [vf, vctx_final] @ W_node^T + b_node  (vctx_final in VCX_A)
    float* vout = out + (size_t)NE * D;
    {
        Batch bt{};
        Job j{};
        j.sg[0] = Seg{vf,          W_node,        1024, 2048, 1024};
        j.sg[1] = Seg{B + O_VCX_A, W_node + 1024, 1024, 2048, 1024};
        j.nseg = 2; j.C = vout; j.ldc = 1024;
        bt.j[0] = j;
        gemm_nt<<<dim3(16, 1, 1), 256>>>(bt);
    }
    k_voutepi<<<64, 256>>>(conn, b_node, vf, vout);
}

// round 3
// speedup vs baseline: 1.2202x; 1.2202x over previous
#include <cuda_runtime.h>
#include <math.h>

// StructureGraphMessagePassing — edge-sparse reformulation.
// FP32 GEMMs using packed fma.rn.f32x2 (FFMA2) inner loop + fused launches.

namespace {
constexpr int D  = 1024;
constexpr int NV = 64;
constexpr int NE = 1024;

constexpr size_t M1 = 1048576;
constexpr size_t O_W14   = 0;
constexpr size_t O_W24   = 1 * M1;
constexpr size_t O_WR2ST = 2 * M1;
constexpr size_t O_WR2OT = 3 * M1;
constexpr size_t O_RCA   = 4 * M1;
constexpr size_t O_RCB   = 5 * M1;
constexpr size_t O_RJ    = 6 * M1;
constexpr size_t O_CC    = 7 * M1;
constexpr size_t O_RELJ  = 8 * M1;
constexpr size_t O_RTRC  = 9 * M1;
constexpr size_t O_VJCAT = 10 * M1;              // 64 x 4096
constexpr size_t SZ      = 65536;                // 64 x 1024
constexpr size_t O_VJ    = O_VJCAT + 262144;
constexpr size_t O_A0    = O_VJ   + SZ;
constexpr size_t O_B0    = O_A0   + SZ;
constexpr size_t O_QS    = O_B0   + SZ;
constexpr size_t O_QO    = O_QS   + SZ;
constexpr size_t O_QS2   = O_QO   + SZ;
constexpr size_t O_QO2   = O_QS2  + SZ;
constexpr size_t O_CTXS  = O_QO2  + SZ;
constexpr size_t O_CTXO  = O_CTXS + SZ;
constexpr size_t O_VCX_A = O_CTXO + SZ;
constexpr size_t O_VCX_B = O_VCX_A + SZ;
constexpr size_t O_SS    = O_VCX_B + SZ;
constexpr size_t O_SO    = O_SS + 1024;
constexpr size_t O_WS    = O_SS + 2048;
constexpr size_t O_WO    = O_SS + 3072;
constexpr size_t TOTAL   = O_SS + 4096;
}  // namespace

__device__ float g_buf[TOTAL];

// ---------------------------------------------------------------------------
// Multi-segment multi-job NT GEMM:  C = sum_s A_s @ B_s^T   (fp32, FFMA2)
// grid = (16, maxMtiles, njobs); jobs with fewer m-tiles early-exit.
// ---------------------------------------------------------------------------
struct Seg { const float* A; const float* B; int lda, ldb, K; };
struct Job { Seg sg[3]; float* C; int ldc; int nseg; int mtiles; };
struct Batch { Job j[6]; };

#define FMA2(c, a, b) \
    asm("fma.rn.f32x2 %0, %1, %2, %0;" : "+l"(c) : "l"(a), "l"(b))

__global__ __launch_bounds__(256, 2) void gemm_nt(Batch batch) {
    const Job job = batch.j[blockIdx.z];
    if ((int)blockIdx.y >= job.mtiles) return;
    __shared__ float As[2][16][128];   // A duplicated along m: {v,v} pairs
    __shared__ float Bs[2][16][64];
    const int tid = threadIdx.x;
    const int tx = tid & 15, ty = tid >> 4;
    const int m0 = blockIdx.y << 6;
    const int n0 = blockIdx.x << 6;
    const int lr = tid >> 2;
    const int lk = (tid & 3) << 2;

    unsigned long long acc[8];
#pragma unroll
    for (int i = 0; i < 8; ++i) acc[i] = 0ull;

    for (int s = 0; s < job.nseg; ++s) {
        const Seg sg = job.sg[s];
        const float* Ap = sg.A + (size_t)(m0 + lr) * sg.lda + lk;
        const float* Bp = sg.B + (size_t)(n0 + lr) * sg.ldb + lk;
        const int T = sg.K >> 4;

        float4 a = *(const float4*)Ap;
        float4 b = *(const float4*)Bp;
        *(float2*)&As[0][lk + 0][lr << 1] = make_float2(a.x, a.x);
        *(float2*)&As[0][lk + 1][lr << 1] = make_float2(a.y, a.y);
        *(float2*)&As[0][lk + 2][lr << 1] = make_float2(a.z, a.z);
        *(float2*)&As[0][lk + 3][lr << 1] = make_float2(a.w, a.w);
        Bs[0][lk + 0][lr] = b.x; Bs[0][lk + 1][lr] = b.y;
        Bs[0][lk + 2][lr] = b.z; Bs[0][lk + 3][lr] = b.w;
        __syncthreads();

        int buf = 0;
        for (int t = 0; t < T; ++t) {
            float4 na, nb;
            if (t + 1 < T) {
                na = *(const float4*)(Ap + (size_t)(t + 1) * 16);
                nb = *(const float4*)(Bp + (size_t)(t + 1) * 16);
            }
#pragma unroll
            for (int kk = 0; kk < 16; ++kk) {
                const ulonglong2 aa = *(const ulonglong2*)&As[buf][kk][ty << 3];
                const ulonglong2 ab = *(const ulonglong2*)&As[buf][kk][(ty << 3) + 4];
                const ulonglong2 bb = *(const ulonglong2*)&Bs[buf][kk][tx << 2];
                FMA2(acc[0], aa.x, bb.x); FMA2(acc[1], aa.x, bb.y);
                FMA2(acc[2], aa.y, bb.x); FMA2(acc[3], aa.y, bb.y);
                FMA2(acc[4], ab.x, bb.x); FMA2(acc[5], ab.x, bb.y);
                FMA2(acc[6], ab.y, bb.x); FMA2(acc[7], ab.y, bb.y);
            }
            if (t + 1 < T) {
                buf ^= 1;
                *(float2*)&As[buf][lk + 0][lr << 1] = make_float2(na.x, na.x);
                *(float2*)&As[buf][lk + 1][lr << 1] = make_float2(na.y, na.y);
                *(float2*)&As[buf][lk + 2][lr << 1] = make_float2(na.z, na.z);
                *(float2*)&As[buf][lk + 3][lr << 1] = make_float2(na.w, na.w);
                Bs[buf][lk + 0][lr] = nb.x; Bs[buf][lk + 1][lr] = nb.y;
                Bs[buf][lk + 2][lr] = nb.z; Bs[buf][lk + 3][lr] = nb.w;
                __syncthreads();
            }
        }
        __syncthreads();
    }

#pragma unroll
    for (int mi = 0; mi < 4; ++mi) {
        float* Crow = job.C + (size_t)(m0 + (ty << 2) + mi) * job.ldc + n0 + (tx << 2);
        *(unsigned long long*)Crow       = acc[2 * mi + 0];
        *(unsigned long long*)(Crow + 2) = acc[2 * mi + 1];
    }
}

// ---------------------------------------------------------------------------
// Glue kernels
// ---------------------------------------------------------------------------
__global__ void k_prep(const float* __restrict__ Wrj,
                       const float* __restrict__ Wr2s,
                       const float* __restrict__ Wr2o,
                       const float* __restrict__ rvf,
                       const float* __restrict__ vf) {
    int idx = blockIdx.x * blockDim.x + threadIdx.x;
    if (idx >= D * D) return;
    int n = idx >> 10, k = idx & 1023;
    const float* row = Wrj + (size_t)n * 4096;
    g_buf[O_W14 + idx] = row[k] + row[3072 + k];
    g_buf[O_W24 + idx] = row[1024 + k] - row[3072 + k];
    g_buf[O_WR2ST + idx] = Wr2s[(size_t)k * 1024 + n];
    g_buf[O_WR2OT + idx] = Wr2o[(size_t)k * 1024 + n];
    g_buf[O_RCA + idx] = rvf[idx];
    if (idx < NV * D) g_buf[O_VCX_A + idx] = vf[idx];
}

// blocks 0..255: vjcat ; blocks 256..4351: rtrc
__global__ void k_elem1(const float* __restrict__ vf, const float* __restrict__ vcx,
                        const float* __restrict__ rvf, const float* __restrict__ rc) {
    int b = blockIdx.x;
    if (b < 256) {
        int idx = b * 256 + threadIdx.x;            // 65536
        int m = idx >> 10, d = idx & 1023;
        float a = vf[idx];
        float c = vcx[idx];
        size_t o = O_VJCAT + (size_t)m * 4096 + d;
        g_buf[o]        = a;
        g_buf[o + 1024] = c;
        g_buf[o + 2048] = a * c;
        g_buf[o + 3072] = c - a;
    } else {
        int idx = (b - 256) * 256 + threadIdx.x;    // 1M
        g_buf[O_RTRC + idx] = rvf[idx] * rc[idx];
    }
}

__global__ void k_relj(const int* __restrict__ eidx) {
    int idx = blockIdx.x * blockDim.x + threadIdx.x;  // 1M
    int e = idx >> 10, d = idx & 1023;
    int ei = eidx[e];
    int i = ei >> 6, j = ei & 63;
    g_buf[O_RELJ + idx] = g_buf[O_A0 + ((size_t)i << 10) + d] +
                          g_buf[O_B0 + ((size_t)j << 10) + d] +
                          g_buf[O_CC + idx];
}

__global__ void k_scores(const int* __restrict__ eidx) {
    int e = blockIdx.x, tid = threadIdx.x;
    int ei = eidx[e];
    int i = ei >> 6, j = ei & 63;
    const float* r = g_buf + O_RELJ + ((size_t)e << 10);
    const float* a = g_buf + O_QS2 + ((size_t)i << 10);
    const float* b = g_buf + O_QO2 + ((size_t)j << 10);
    float s1 = 0.f, s2 = 0.f;
    for (int d = tid; d < 1024; d += 256) {
        float rv = r[d];
        s1 += a[d] * rv;
        s2 += b[d] * rv;
    }
    __shared__ float sh[2][256];
    sh[0][tid] = s1; sh[1][tid] = s2;
    __syncthreads();
    for (int st = 128; st > 0; st >>= 1) {
        if (tid < st) { sh[0][tid] += sh[0][tid + st]; sh[1][tid] += sh[1][tid + st]; }
        __syncthreads();
    }
    if (tid == 0) {
        g_buf[O_SS + e] = sh[0][0] * 0.03125f;
        g_buf[O_SO + e] = sh[1][0] * 0.03125f;
    }
}

__global__ void k_softmax(const int* __restrict__ conn) {
    int b = blockIdx.x, lane = threadIdx.x;
    bool isRow = b < 64;
    int idx = isRow ? b : b - 64;
    int e0 = isRow ? conn[idx * 64 + lane]      : conn[lane * 64 + idx];
    int e1 = isRow ? conn[idx * 64 + lane + 32] : conn[(lane + 32) * 64 + idx];
    size_t so = isRow ? O_SS : O_SO;
    float v0 = (e0 >= 0) ? g_buf[so + e0] : -1e30f;
    float v1 = (e1 >= 0) ? g_buf[so + e1] : -1e30f;
    float m = fmaxf(v0, v1);
    for (int o = 16; o > 0; o >>= 1) m = fmaxf(m, __shfl_xor_sync(0xffffffffu, m, o));
    float x0 = (e0 >= 0) ? expf(v0 - m) : 0.f;
    float x1 = (e1 >= 0) ? expf(v1 - m) : 0.f;
    float s = x0 + x1;
    for (int o = 16; o > 0; o >>= 1) s += __shfl_xor_sync(0xffffffffu, s, o);
    float inv = 1.f / s;
    size_t wo = isRow ? O_WS : O_WO;
    if (e0 >= 0) g_buf[wo + e0] = x0 * inv;
    if (e1 >= 0) g_buf[wo + e1] = x1 * inv;
}

__global__ void k_ctx(const int* __restrict__ conn) {
    int n = blockIdx.x, tid = threadIdx.x;
    float accS[4] = {0.f, 0.f, 0.f, 0.f};
    float accO[4] = {0.f, 0.f, 0.f, 0.f};
    for (int p = 0; p < 64; ++p) {
        int eS = conn[n * 64 + p];
        if (eS >= 0) {
            float w = g_buf[O_WS + eS];
            const float* r = g_buf + O_RELJ + ((size_t)eS << 10);
#pragma unroll
            for (int c = 0; c < 4; ++c) accS[c] += w * r[tid + 256 * c];
        }
        int eO = conn[p * 64 + n];
        if (eO >= 0) {
            float w = g_buf[O_WO + eO];
            const float* r = g_buf + O_RELJ + ((size_t)eO << 10);
#pragma unroll
            for (int c = 0; c < 4; ++c) accO[c] += w * r[tid + 256 * c];
        }
    }
#pragma unroll
    for (int c = 0; c < 4; ++c) {
        int d = tid + 256 * c;
        g_buf[O_CTXS + ((size_t)n << 10) + d] = accS[c];
        g_buf[O_CTXO + ((size_t)n << 10) + d] = accO[c];
    }
}

__global__ void k_voutepi(const int* __restrict__ conn,
                          const float* __restrict__ bnode,
                          const float* __restrict__ vf,
                          float* __restrict__ vout) {
    int i = blockIdx.x, tid = threadIdx.x;
    __shared__ int s_deg;
    if (tid == 0) {
        int dc = 0;
        for (int p = 0; p < 64; ++p)
            dc += (conn[i * 64 + p] >= 0) + (conn[p * 64 + i] >= 0);
        s_deg = dc;
    }
    __syncthreads();
    for (int d = tid; d < 1024; d += 256) {
        float v = vout[((size_t)i << 10) + d] + bnode[d];
        if (s_deg == 0) v = vf[((size_t)i << 10) + d];
        vout[((size_t)i << 10) + d] = v;
    }
}

// ---------------------------------------------------------------------------
static inline Job mkjob1(const float* A, const float* Bm, int lda, int ldb, int K,
                         float* C, int ldc, int mtiles) {
    Job j{};
    j.sg[0] = Seg{A, Bm, lda, ldb, K};
    j.nseg = 1; j.C = C; j.ldc = ldc; j.mtiles = mtiles;
    return j;
}

extern "C" void kernel_launch(void* const* d_in, const int* in_sizes, int n_in,
                              void* d_out, int out_size) {
    (void)in_sizes; (void)n_in; (void)out_size;
    const float* vf     = (const float*)d_in[0];
    const float* rvf    = (const float*)d_in[1];
    const int*   conn   = (const int*)d_in[2];
    const int*   eidx   = (const int*)d_in[4];
    const float* W_sub  = (const float*)d_in[5];
    const float* W_obj  = (const float*)d_in[6];
    const float* W_joint= (const float*)d_in[9];
    const float* W_ctx  = (const float*)d_in[10];
    const float* W_ru   = (const float*)d_in[11];
    const float* W_rj   = (const float*)d_in[12];
    const float* W_rc   = (const float*)d_in[13];
    const float* W_node = (const float*)d_in[14];
    const float* b_node = (const float*)d_in[15];
    const float* W_fac  = (const float*)d_in[16];
    float* out = (float*)d_out;

    float* B = nullptr;
    cudaGetSymbolAddress((void**)&B, g_buf);

    k_prep<<<4096, 256>>>(W_rj, (const float*)d_in[7], (const float*)d_in[8], rvf, vf);

    for (int t = 0; t < 2; ++t) {
        float* rcIn   = B + (t == 0 ? O_RCA : O_RCB);
        float* rcOut  = B + (t == 0 ? O_RCB : O_RCA);
        float* vcxIn  = B + (t == 0 ? O_VCX_A : O_VCX_B);
        float* vcxOut = B + (t == 0 ? O_VCX_B : O_VCX_A);

        k_elem1<<<4352, 256>>>(vf, vcxIn, rvf, rcIn);

        // Launch A: vj (1x16) + rj (16x16, 3 segs)
        {
            Batch bt{};
            bt.j[0] = mkjob1(B + O_VJCAT, W_joint, 4096, 4096, 4096, B + O_VJ, 1024, 1);
            Job j{};
            j.sg[0] = Seg{rvf,        B + O_W14,   1024, 1024, 1024};
            j.sg[1] = Seg{rcIn,       B + O_W24,   1024, 1024, 1024};
            j.sg[2] = Seg{B + O_RTRC, W_rj + 2048, 1024, 4096, 1024};
            j.nseg = 3; j.C = B + O_RJ; j.ldc = 1024; j.mtiles = 16;
            bt.j[1] = j;
            gemm_nt<<<dim3(16, 16, 2), 256>>>(bt);
        }

        // Launch B: cc (16x16) + A0,B0,QS,QO (1x16 each)
        {
            Batch bt{};
            bt.j[0] = mkjob1(B + O_RJ, W_ru + 2048, 1024, 3072, 1024, B + O_CC, 1024, 16);
            bt.j[1] = mkjob1(B + O_VJ, W_ru,        1024, 3072, 1024, B + O_A0, 1024, 1);
            bt.j[2] = mkjob1(B + O_VJ, W_ru + 1024, 1024, 3072, 1024, B + O_B0, 1024, 1);
            bt.j[3] = mkjob1(B + O_VJ, W_sub,       1024, 1024, 1024, B + O_QS, 1024, 1);
            bt.j[4] = mkjob1(B + O_VJ, W_obj,       1024, 1024, 1024, B + O_QO, 1024, 1);
            gemm_nt<<<dim3(16, 16, 5), 256>>>(bt);
        }

        // Launch C: qs2, qo2
        {
            Batch bt{};
            bt.j[0] = mkjob1(B + O_QS, B + O_WR2ST, 1024, 1024, 1024, B + O_QS2, 1024, 1);
            bt.j[1] = mkjob1(B + O_QO, B + O_WR2OT, 1024, 1024, 1024, B + O_QO2, 1024, 1);
            gemm_nt<<<dim3(16, 1, 2), 256>>>(bt);
        }

        k_relj<<<4096, 256>>>(eidx);
        k_scores<<<1024, 256>>>(eidx);
        k_softmax<<<128, 32>>>(conn);
        k_ctx<<<64, 256>>>(conn);

        // Launch D: vctx' (1x16, 3 segs) + rc' (16x16, 2 segs)
        {
            Batch bt{};
            Job jv{};
            jv.sg[0] = Seg{vcxIn,      W_ctx,        1024, 3072, 1024};
            jv.sg[1] = Seg{B + O_CTXS, W_ctx + 1024, 1024, 3072, 1024};
            jv.sg[2] = Seg{B + O_CTXO, W_ctx + 2048, 1024, 3072, 1024};
            jv.nseg = 3; jv.C = vcxOut; jv.ldc = 1024; jv.mtiles = 1;
            bt.j[0] = jv;
            Job jr{};
            jr.sg[0] = Seg{rcIn,       W_rc,        1024, 2048, 1024};
            jr.sg[1] = Seg{B + O_RELJ, W_rc + 1024, 1024, 2048, 1024};
            jr.nseg = 2; jr.C = rcOut; jr.ldc = 1024; jr.mtiles = 16;
            bt.j[1] = jr;
            gemm_nt<<<dim3(16, 16, 2), 256>>>(bt);
        }
    }

    // Final: rel_out (16x16, 2 segs) + v_out (1x16, 2 segs)
    float* vout = out + (size_t)NE * D;
    {
        Batch bt{};
        Job jr{};
        jr.sg[0] = Seg{rvf,       W_fac,        1024, 2048, 1024};
        jr.sg[1] = Seg{B + O_RCA, W_fac + 1024, 1024, 2048, 1024};
        jr.nseg = 2; jr.C = out; jr.ldc = 1024; jr.mtiles = 16;
        bt.j[0] = jr;
        Job jv{};
        jv.sg[0] = Seg{vf,          W_node,        1024, 2048, 1024};
        jv.sg[1] = Seg{B + O_VCX_A, W_node + 1024, 1024, 2048, 1024};
        jv.nseg = 2; jv.C = vout; jv.ldc = 1024; jv.mtiles = 1;
        bt.j[1] = jv;
        gemm_nt<<<dim3(16, 16, 2), 256>>>(bt);
    }
    k_voutepi<<<64, 256>>>(conn, b_node, vf, vout);
}

// round 5
// speedup vs baseline: 2.3837x; 1.9535x over previous
#include <cuda_runtime.h>
#include <cuda_bf16.h>
#include <stdint.h>
#include <math.h>

// StructureGraphMessagePassing — edge-sparse reformulation.
// GEMMs via warp-level mma.sync bf16 (split-3: hi*hi + hi*lo + lo*hi), fp32 accum.

namespace {
constexpr int D  = 1024;
constexpr int NV = 64;
constexpr int NE = 1024;

constexpr size_t M1 = 1048576;
constexpr size_t O_W14   = 0;
constexpr size_t O_W24   = 1 * M1;
constexpr size_t O_WR2ST = 2 * M1;
constexpr size_t O_WR2OT = 3 * M1;
constexpr size_t O_RCA   = 4 * M1;
constexpr size_t O_RCB   = 5 * M1;
constexpr size_t O_RJ    = 6 * M1;
constexpr size_t O_CC    = 7 * M1;
constexpr size_t O_RELJ  = 8 * M1;
constexpr size_t O_RTRC  = 9 * M1;
constexpr size_t O_VJCAT = 10 * M1;              // 64 x 4096
constexpr size_t SZ      = 65536;                // 64 x 1024
constexpr size_t O_VJ    = O_VJCAT + 262144;
constexpr size_t O_A0    = O_VJ   + SZ;
constexpr size_t O_B0    = O_A0   + SZ;
constexpr size_t O_QS    = O_B0   + SZ;
constexpr size_t O_QO    = O_QS   + SZ;
constexpr size_t O_QS2   = O_QO   + SZ;
constexpr size_t O_QO2   = O_QS2  + SZ;
constexpr size_t O_CTXS  = O_QO2  + SZ;
constexpr size_t O_CTXO  = O_CTXS + SZ;
constexpr size_t O_VCX_A = O_CTXO + SZ;
constexpr size_t O_VCX_B = O_VCX_A + SZ;
constexpr size_t O_SS    = O_VCX_B + SZ;
constexpr size_t O_SO    = O_SS + 1024;
constexpr size_t O_WS    = O_SS + 2048;
constexpr size_t O_WO    = O_SS + 3072;
constexpr size_t TOTAL   = O_SS + 4096;
}  // namespace

__device__ float g_buf[TOTAL];

// ---------------------------------------------------------------------------
__device__ __forceinline__ uint32_t smem_u32(const void* p) {
    uint32_t a;
    asm("{ .reg .u64 t; cvta.to.shared.u64 t, %1; cvt.u32.u64 %0, t; }"
        : "=r"(a) : "l"(p));
    return a;
}

#define LDSM4(r0, r1, r2, r3, addr) \
    asm volatile("ldmatrix.sync.aligned.m8n8.x4.shared.b16 {%0,%1,%2,%3}, [%4];" \
                 : "=r"(r0), "=r"(r1), "=r"(r2), "=r"(r3) : "r"(addr))

#define MMA16816(c, a, b0, b1) \
    asm volatile("mma.sync.aligned.m16n8k16.row.col.f32.bf16.bf16.f32 " \
                 "{%0,%1,%2,%3}, {%4,%5,%6,%7}, {%8,%9}, {%0,%1,%2,%3};" \
                 : "+f"((c)[0]), "+f"((c)[1]), "+f"((c)[2]), "+f"((c)[3]) \
                 : "r"((a)[0]), "r"((a)[1]), "r"((a)[2]), "r"((a)[3]), \
                   "r"(b0), "r"(b1))

// smem tile: rows of 64B (32 bf16). 16B-unit swizzle: h' = h ^ ((r>>1)&3)
__device__ __forceinline__ int soff(int r, int h) {
    return r * 64 + ((h ^ ((r >> 1) & 3)) << 4);
}

// ---------------------------------------------------------------------------
// Multi-segment multi-job NT GEMM:  C = sum_s A_s @ B_s^T
// Block tile 128(M) x 64(N), K-chunks of 32, bf16 hi/lo split-3, fp32 accum.
// grid = (N/64, maxMtiles, njobs)
// ---------------------------------------------------------------------------
struct Seg { const float* A; const float* B; int lda, ldb, K; };
struct Job { Seg sg[3]; float* C; int ldc; int nseg; int mtiles; int M; };
struct Batch { Job j[6]; };

// per-stage layout inside sm[buf]: Ahi 0 (8KB), Alo 8192, Bhi 16384 (4KB), Blo 20480
__global__ __launch_bounds__(256) void tc_gemm(Batch batch) {
    const Job job = batch.j[blockIdx.z];
    if ((int)blockIdx.y >= job.mtiles) return;
    __shared__ __align__(128) char sm[2][24576];

    const int tid = threadIdx.x;
    const int wid = tid >> 5;
    const int lane = tid & 31;
    const int wm = wid >> 1;            // 0..3
    const int wn = wid & 1;             // 0..1
    const int m0 = blockIdx.y << 7;
    const int n0 = blockIdx.x << 6;
    const int rows_valid = job.M - m0;  // <=128 rows valid in this m-tile

    // ldmatrix lane address components
    const int arow_l = (lane & 7) + ((lane >> 3) & 1) * 8;
    const int ah_l   = (lane >> 4) & 1;
    const int brow_l = (lane & 7) + ((lane >> 4) & 1) * 8;
    const int bh_l   = (lane >> 3) & 1;

    float c[2][4][4];
#pragma unroll
    for (int a = 0; a < 2; ++a)
#pragma unroll
        for (int b = 0; b < 4; ++b)
#pragma unroll
            for (int q = 0; q < 4; ++q) c[a][b][q] = 0.f;

    // prefetch lane mapping: A: idx = tid + i*256 (i<4) -> row idx>>3, q idx&7
    //                        B: idx = tid (i<2)        -> row idx>>3, q idx&7
    int total = 0;
#pragma unroll
    for (int s = 0; s < 3; ++s) if (s < job.nseg) total += job.sg[s].K >> 5;

    // ---- fill stage 0 ----
    {
        const Seg sg = job.sg[0];
        char* dst = sm[0];
#pragma unroll
        for (int i = 0; i < 4; ++i) {
            int idx = tid + (i << 8);
            int row = idx >> 3, q = idx & 7;
            float4 v = make_float4(0.f, 0.f, 0.f, 0.f);
            if (row < rows_valid)
                v = *(const float4*)(sg.A + (size_t)(m0 + row) * sg.lda + (q << 2));
            __nv_bfloat162 h0 = __floats2bfloat162_rn(v.x, v.y);
            __nv_bfloat162 h1 = __floats2bfloat162_rn(v.z, v.w);
            __nv_bfloat162 l0 = __floats2bfloat162_rn(v.x - __low2float(h0), v.y - __high2float(h0));
            __nv_bfloat162 l1 = __floats2bfloat162_rn(v.z - __low2float(h1), v.w - __high2float(h1));
            int off = soff(row, q >> 1) + (q & 1) * 8;
            *(uint2*)(dst + off)        = make_uint2(*(uint32_t*)&h0, *(uint32_t*)&h1);
            *(uint2*)(dst + 8192 + off) = make_uint2(*(uint32_t*)&l0, *(uint32_t*)&l1);
        }
#pragma unroll
        for (int i = 0; i < 2; ++i) {
            int idx = tid + (i << 8);
            int row = idx >> 3, q = idx & 7;
            float4 v = *(const float4*)(sg.B + (size_t)(n0 + row) * sg.ldb + (q << 2));
            __nv_bfloat162 h0 = __floats2bfloat162_rn(v.x, v.y);
            __nv_bfloat162 h1 = __floats2bfloat162_rn(v.z, v.w);
            __nv_bfloat162 l0 = __floats2bfloat162_rn(v.x - __low2float(h0), v.y - __high2float(h0));
            __nv_bfloat162 l1 = __floats2bfloat162_rn(v.z - __low2float(h1), v.w - __high2float(h1));
            int off = soff(row, q >> 1) + (q & 1) * 8;
            *(uint2*)(dst + 16384 + off) = make_uint2(*(uint32_t*)&h0, *(uint32_t*)&h1);
            *(uint2*)(dst + 20480 + off) = make_uint2(*(uint32_t*)&l0, *(uint32_t*)&l1);
        }
    }
    __syncthreads();

    int s = 0, ch = 0;
    for (int t = 0; t < total; ++t) {
        // next coordinates
        int s2 = s, ch2 = ch + 1;
        if (ch2 == (job.sg[s].K >> 5)) { s2 = s + 1; ch2 = 0; }
        const bool hasNext = (s2 < job.nseg);

        // ---- prefetch next chunk to registers ----
        float4 pa[4], pb[2];
        if (hasNext) {
            const Seg sg = job.sg[s2];
            const int k0 = ch2 << 5;
#pragma unroll
            for (int i = 0; i < 4; ++i) {
                int idx = tid + (i << 8);
                int row = idx >> 3, q = idx & 7;
                pa[i] = make_float4(0.f, 0.f, 0.f, 0.f);
                if (row < rows_valid)
                    pa[i] = *(const float4*)(sg.A + (size_t)(m0 + row) * sg.lda + k0 + (q << 2));
            }
#pragma unroll
            for (int i = 0; i < 2; ++i) {
                int idx = tid + (i << 8);
                int row = idx >> 3, q = idx & 7;
                pb[i] = *(const float4*)(sg.B + (size_t)(n0 + row) * sg.ldb + k0 + (q << 2));
            }
        }

        // ---- compute from sm[t&1] ----
        {
            const uint32_t sb = smem_u32(sm[t & 1]);
#pragma unroll
            for (int ksub = 0; ksub < 2; ++ksub) {
                const int hb = ksub << 1;
                uint32_t ah[2][4], al[2][4], bh[2][4], bl[2][4];
#pragma unroll
                for (int mi = 0; mi < 2; ++mi) {
                    int row = wm * 32 + mi * 16 + arow_l;
                    uint32_t ad = sb + soff(row, ah_l + hb);
                    LDSM4(ah[mi][0], ah[mi][1], ah[mi][2], ah[mi][3], ad);
                    LDSM4(al[mi][0], al[mi][1], al[mi][2], al[mi][3], ad + 8192);
                }
#pragma unroll
                for (int g = 0; g < 2; ++g) {
                    int row = wn * 32 + g * 16 + brow_l;
                    uint32_t bd = sb + 16384 + soff(row, bh_l + hb);
                    LDSM4(bh[g][0], bh[g][1], bh[g][2], bh[g][3], bd);
                    LDSM4(bl[g][0], bl[g][1], bl[g][2], bl[g][3], bd + 4096);
                }
#pragma unroll
                for (int mi = 0; mi < 2; ++mi)
#pragma unroll
                    for (int g = 0; g < 2; ++g)
#pragma unroll
                        for (int j = 0; j < 2; ++j) {
                            const int ni = g * 2 + j;
                            MMA16816(c[mi][ni], ah[mi], bh[g][2 * j], bh[g][2 * j + 1]);
                            MMA16816(c[mi][ni], ah[mi], bl[g][2 * j], bl[g][2 * j + 1]);
                            MMA16816(c[mi][ni], al[mi], bh[g][2 * j], bh[g][2 * j + 1]);
                        }
            }
        }

        // ---- store prefetched chunk into sm[(t+1)&1] ----
        if (hasNext) {
            char* dst = sm[(t + 1) & 1];
#pragma unroll
            for (int i = 0; i < 4; ++i) {
                int idx = tid + (i << 8);
                int row = idx >> 3, q = idx & 7;
                float4 v = pa[i];
                __nv_bfloat162 h0 = __floats2bfloat162_rn(v.x, v.y);
                __nv_bfloat162 h1 = __floats2bfloat162_rn(v.z, v.w);
                __nv_bfloat162 l0 = __floats2bfloat162_rn(v.x - __low2float(h0), v.y - __high2float(h0));
                __nv_bfloat162 l1 = __floats2bfloat162_rn(v.z - __low2float(h1), v.w - __high2float(h1));
                int off = soff(row, q >> 1) + (q & 1) * 8;
                *(uint2*)(dst + off)        = make_uint2(*(uint32_t*)&h0, *(uint32_t*)&h1);
                *(uint2*)(dst + 8192 + off) = make_uint2(*(uint32_t*)&l0, *(uint32_t*)&l1);
            }
#pragma unroll
            for (int i = 0; i < 2; ++i) {
                int idx = tid + (i << 8);
                int row = idx >> 3, q = idx & 7;
                float4 v = pb[i];
                __nv_bfloat162 h0 = __floats2bfloat162_rn(v.x, v.y);
                __nv_bfloat162 h1 = __floats2bfloat162_rn(v.z, v.w);
                __nv_bfloat162 l0 = __floats2bfloat162_rn(v.x - __low2float(h0), v.y - __high2float(h0));
                __nv_bfloat162 l1 = __floats2bfloat162_rn(v.z - __low2float(h1), v.w - __high2float(h1));
                int off = soff(row, q >> 1) + (q & 1) * 8;
                *(uint2*)(dst + 16384 + off) = make_uint2(*(uint32_t*)&h0, *(uint32_t*)&h1);
                *(uint2*)(dst + 20480 + off) = make_uint2(*(uint32_t*)&l0, *(uint32_t*)&l1);
            }
        }
        __syncthreads();
        s = s2; ch = ch2;
    }

    // ---- epilogue ----
    if (wm * 32 < rows_valid) {
#pragma unroll
        for (int mi = 0; mi < 2; ++mi) {
            int rbase = m0 + wm * 32 + mi * 16 + (lane >> 2);
#pragma unroll
            for (int ni = 0; ni < 4; ++ni) {
                int col = n0 + wn * 32 + ni * 8 + (lane & 3) * 2;
                *(float2*)(job.C + (size_t)rbase * job.ldc + col) =
                    make_float2(c[mi][ni][0], c[mi][ni][1]);
                *(float2*)(job.C + (size_t)(rbase + 8) * job.ldc + col) =
                    make_float2(c[mi][ni][2], c[mi][ni][3]);
            }
        }
    }
}

// ---------------------------------------------------------------------------
// Glue kernels (fp32)
// ---------------------------------------------------------------------------
__global__ void k_prep(const float* __restrict__ Wrj,
                       const float* __restrict__ Wr2s,
                       const float* __restrict__ Wr2o,
                       const float* __restrict__ rvf,
                       const float* __restrict__ vf) {
    int idx = blockIdx.x * blockDim.x + threadIdx.x;
    if (idx >= D * D) return;
    int n = idx >> 10, k = idx & 1023;
    const float* row = Wrj + (size_t)n * 4096;
    g_buf[O_W14 + idx] = row[k] + row[3072 + k];
    g_buf[O_W24 + idx] = row[1024 + k] - row[3072 + k];
    g_buf[O_WR2ST + idx] = Wr2s[(size_t)k * 1024 + n];
    g_buf[O_WR2OT + idx] = Wr2o[(size_t)k * 1024 + n];
    g_buf[O_RCA + idx] = rvf[idx];
    if (idx < NV * D) g_buf[O_VCX_A + idx] = vf[idx];
}

__global__ void k_elem1(const float* __restrict__ vf, const float* __restrict__ vcx,
                        const float* __restrict__ rvf, const float* __restrict__ rc) {
    int b = blockIdx.x;
    if (b < 256) {
        int idx = b * 256 + threadIdx.x;
        int m = idx >> 10, d = idx & 1023;
        float a = vf[idx];
        float c = vcx[idx];
        size_t o = O_VJCAT + (size_t)m * 4096 + d;
        g_buf[o]        = a;
        g_buf[o + 1024] = c;
        g_buf[o + 2048] = a * c;
        g_buf[o + 3072] = c - a;
    } else {
        int idx = (b - 256) * 256 + threadIdx.x;
        g_buf[O_RTRC + idx] = rvf[idx] * rc[idx];
    }
}

__global__ void k_relj(const int* __restrict__ eidx) {
    int idx = blockIdx.x * blockDim.x + threadIdx.x;
    int e = idx >> 10, d = idx & 1023;
    int ei = eidx[e];
    int i = ei >> 6, j = ei & 63;
    g_buf[O_RELJ + idx] = g_buf[O_A0 + ((size_t)i << 10) + d] +
                          g_buf[O_B0 + ((size_t)j << 10) + d] +
                          g_buf[O_CC + idx];
}

__global__ void k_scores(const int* __restrict__ eidx) {
    int e = blockIdx.x, tid = threadIdx.x;
    int ei = eidx[e];
    int i = ei >> 6, j = ei & 63;
    const float* r = g_buf + O_RELJ + ((size_t)e << 10);
    const float* a = g_buf + O_QS2 + ((size_t)i << 10);
    const float* b = g_buf + O_QO2 + ((size_t)j << 10);
    float s1 = 0.f, s2 = 0.f;
    for (int d = tid; d < 1024; d += 256) {
        float rv = r[d];
        s1 += a[d] * rv;
        s2 += b[d] * rv;
    }
    __shared__ float sh[2][256];
    sh[0][tid] = s1; sh[1][tid] = s2;
    __syncthreads();
    for (int st = 128; st > 0; st >>= 1) {
        if (tid < st) { sh[0][tid] += sh[0][tid + st]; sh[1][tid] += sh[1][tid + st]; }
        __syncthreads();
    }
    if (tid == 0) {
        g_buf[O_SS + e] = sh[0][0] * 0.03125f;
        g_buf[O_SO + e] = sh[1][0] * 0.03125f;
    }
}

__global__ void k_softmax(const int* __restrict__ conn) {
    int b = blockIdx.x, lane = threadIdx.x;
    bool isRow = b < 64;
    int idx = isRow ? b : b - 64;
    int e0 = isRow ? conn[idx * 64 + lane]      : conn[lane * 64 + idx];
    int e1 = isRow ? conn[idx * 64 + lane + 32] : conn[(lane + 32) * 64 + idx];
    size_t so = isRow ? O_SS : O_SO;
    float v0 = (e0 >= 0) ? g_buf[so + e0] : -1e30f;
    float v1 = (e1 >= 0) ? g_buf[so + e1] : -1e30f;
    float m = fmaxf(v0, v1);
    for (int o = 16; o > 0; o >>= 1) m = fmaxf(m, __shfl_xor_sync(0xffffffffu, m, o));
    float x0 = (e0 >= 0) ? expf(v0 - m) : 0.f;
    float x1 = (e1 >= 0) ? expf(v1 - m) : 0.f;
    float s = x0 + x1;
    for (int o = 16; o > 0; o >>= 1) s += __shfl_xor_sync(0xffffffffu, s, o);
    float inv = 1.f / s;
    size_t wo = isRow ? O_WS : O_WO;
    if (e0 >= 0) g_buf[wo + e0] = x0 * inv;
    if (e1 >= 0) g_buf[wo + e1] = x1 * inv;
}

__global__ void k_ctx(const int* __restrict__ conn) {
    int n = blockIdx.x, tid = threadIdx.x;
    float accS[4] = {0.f, 0.f, 0.f, 0.f};
    float accO[4] = {0.f, 0.f, 0.f, 0.f};
    for (int p = 0; p < 64; ++p) {
        int eS = conn[n * 64 + p];
        if (eS >= 0) {
            float w = g_buf[O_WS + eS];
            const float* r = g_buf + O_RELJ + ((size_t)eS << 10);
#pragma unroll
            for (int c = 0; c < 4; ++c) accS[c] += w * r[tid + 256 * c];
        }
        int eO = conn[p * 64 + n];
        if (eO >= 0) {
            float w = g_buf[O_WO + eO];
            const float* r = g_buf + O_RELJ + ((size_t)eO << 10);
#pragma unroll
            for (int c = 0; c < 4; ++c) accO[c] += w * r[tid + 256 * c];
        }
    }
#pragma unroll
    for (int c = 0; c < 4; ++c) {
        int d = tid + 256 * c;
        g_buf[O_CTXS + ((size_t)n << 10) + d] = accS[c];
        g_buf[O_CTXO + ((size_t)n << 10) + d] = accO[c];
    }
}

__global__ void k_voutepi(const int* __restrict__ conn,
                          const float* __restrict__ bnode,
                          const float* __restrict__ vf,
                          float* __restrict__ vout) {
    int i = blockIdx.x, tid = threadIdx.x;
    __shared__ int s_deg;
    if (tid == 0) {
        int dc = 0;
        for (int p = 0; p < 64; ++p)
            dc += (conn[i * 64 + p] >= 0) + (conn[p * 64 + i] >= 0);
        s_deg = dc;
    }
    __syncthreads();
    for (int d = tid; d < 1024; d += 256) {
        float v = vout[((size_t)i << 10) + d] + bnode[d];
        if (s_deg == 0) v = vf[((size_t)i << 10) + d];
        vout[((size_t)i << 10) + d] = v;
    }
}

// ---------------------------------------------------------------------------
static inline Job mkjob1(const float* A, const float* Bm, int lda, int ldb, int K,
                         float* C, int ldc, int M) {
    Job j{};
    j.sg[0] = Seg{A, Bm, lda, ldb, K};
    j.nseg = 1; j.C = C; j.ldc = ldc; j.M = M; j.mtiles = (M + 127) / 128;
    return j;
}

extern "C" void kernel_launch(void* const* d_in, const int* in_sizes, int n_in,
                              void* d_out, int out_size) {
    (void)in_sizes; (void)n_in; (void)out_size;
    const float* vf     = (const float*)d_in[0];
    const float* rvf    = (const float*)d_in[1];
    const int*   conn   = (const int*)d_in[2];
    const int*   eidx   = (const int*)d_in[4];
    const float* W_sub  = (const float*)d_in[5];
    const float* W_obj  = (const float*)d_in[6];
    const float* W_joint= (const float*)d_in[9];
    const float* W_ctx  = (const float*)d_in[10];
    const float* W_ru   = (const float*)d_in[11];
    const float* W_rj   = (const float*)d_in[12];
    const float* W_rc   = (const float*)d_in[13];
    const float* W_node = (const float*)d_in[14];
    const float* b_node = (const float*)d_in[15];
    const float* W_fac  = (const float*)d_in[16];
    float* out = (float*)d_out;

    float* B = nullptr;
    cudaGetSymbolAddress((void**)&B, g_buf);

    k_prep<<<4096, 256>>>(W_rj, (const float*)d_in[7], (const float*)d_in[8], rvf, vf);

    for (int t = 0; t < 2; ++t) {
        float* rcIn   = B + (t == 0 ? O_RCA : O_RCB);
        float* rcOut  = B + (t == 0 ? O_RCB : O_RCA);
        float* vcxIn  = B + (t == 0 ? O_VCX_A : O_VCX_B);
        float* vcxOut = B + (t == 0 ? O_VCX_B : O_VCX_A);

        k_elem1<<<4352, 256>>>(vf, vcxIn, rvf, rcIn);

        // Launch A: vj (M=64, K=4096) + rj (M=1024, 3 segs)
        {
            Batch bt{};
            bt.j[0] = mkjob1(B + O_VJCAT, W_joint, 4096, 4096, 4096, B + O_VJ, 1024, 64);
            Job j{};
            j.sg[0] = Seg{rvf,        B + O_W14,   1024, 1024, 1024};
            j.sg[1] = Seg{rcIn,       B + O_W24,   1024, 1024, 1024};
            j.sg[2] = Seg{B + O_RTRC, W_rj + 2048, 1024, 4096, 1024};
            j.nseg = 3; j.C = B + O_RJ; j.ldc = 1024; j.M = 1024; j.mtiles = 8;
            bt.j[1] = j;
            tc_gemm<<<dim3(16, 8, 2), 256>>>(bt);
        }

        // Launch B: cc (M=1024) + A0,B0,QS,QO (M=64)
        {
            Batch bt{};
            bt.j[0] = mkjob1(B + O_RJ, W_ru + 2048, 1024, 3072, 1024, B + O_CC, 1024, 1024);
            bt.j[1] = mkjob1(B + O_VJ, W_ru,        1024, 3072, 1024, B + O_A0, 1024, 64);
            bt.j[2] = mkjob1(B + O_VJ, W_ru + 1024, 1024, 3072, 1024, B + O_B0, 1024, 64);
            bt.j[3] = mkjob1(B + O_VJ, W_sub,       1024, 1024, 1024, B + O_QS, 1024, 64);
            bt.j[4] = mkjob1(B + O_VJ, W_obj,       1024, 1024, 1024, B + O_QO, 1024, 64);
            tc_gemm<<<dim3(16, 8, 5), 256>>>(bt);
        }

        // Launch C: qs2, qo2
        {
            Batch bt{};
            bt.j[0] = mkjob1(B + O_QS, B + O_WR2ST, 1024, 1024, 1024, B + O_QS2, 1024, 64);
            bt.j[1] = mkjob1(B + O_QO, B + O_WR2OT, 1024, 1024, 1024, B + O_QO2, 1024, 64);
            tc_gemm<<<dim3(16, 1, 2), 256>>>(bt);
        }

        k_relj<<<4096, 256>>>(eidx);
        k_scores<<<1024, 256>>>(eidx);
        k_softmax<<<128, 32>>>(conn);
        k_ctx<<<64, 256>>>(conn);

        // Launch D: vctx' (M=64, 3 segs) + rc' (M=1024, 2 segs)
        {
            Batch bt{};
            Job jv{};
            jv.sg[0] = Seg{vcxIn,      W_ctx,        1024, 3072, 1024};
            jv.sg[1] = Seg{B + O_CTXS, W_ctx + 1024, 1024, 3072, 1024};
            jv.sg[2] = Seg{B + O_CTXO, W_ctx + 2048, 1024, 3072, 1024};
            jv.nseg = 3; jv.C = vcxOut; jv.ldc = 1024; jv.M = 64; jv.mtiles = 1;
            bt.j[0] = jv;
            Job jr{};
            jr.sg[0] = Seg{rcIn,       W_rc,        1024, 2048, 1024};
            jr.sg[1] = Seg{B + O_RELJ, W_rc + 1024, 1024, 2048, 1024};
            jr.nseg = 2; jr.C = rcOut; jr.ldc = 1024; jr.M = 1024; jr.mtiles = 8;
            bt.j[1] = jr;
            tc_gemm<<<dim3(16, 8, 2), 256>>>(bt);
        }
    }

    // Final: rel_out (M=1024, 2 segs) + v_out (M=64, 2 segs)
    float* vout = out + (size_t)NE * D;
    {
        Batch bt{};
        Job jr{};
        jr.sg[0] = Seg{rvf,       W_fac,        1024, 2048, 1024};
        jr.sg[1] = Seg{B + O_RCA, W_fac + 1024, 1024, 2048, 1024};
        jr.nseg = 2; jr.C = out; jr.ldc = 1024; jr.M = 1024; jr.mtiles = 8;
        bt.j[0] = jr;
        Job jv{};
        jv.sg[0] = Seg{vf,          W_node,        1024, 2048, 1024};
        jv.sg[1] = Seg{B + O_VCX_A, W_node + 1024, 1024, 2048, 1024};
        jv.nseg = 2; jv.C = vout; jv.ldc = 1024; jv.M = 64; jv.mtiles = 1;
        bt.j[1] = jv;
        tc_gemm<<<dim3(16, 8, 2), 256>>>(bt);
    }
    k_voutepi<<<64, 256>>>(conn, b_node, vf, vout);
}